// round 5
// baseline (speedup 1.0000x reference)
#include <cuda_runtime.h>
#include <cuda_bf16.h>

#define BATCH 4096
#define TT    1024
#define NVOC  32000
#define HID   16

typedef unsigned long long ull;

// Scratch (device globals: allocation-free rule)
__device__ float g_xtab[NVOC * HID];   // 2MB: precomputed x-projection per token
__device__ float g_hfin[BATCH * HID];  // 256KB: final hidden states

// ---- packed f32x2 helpers on 64-bit registers ----
__device__ __forceinline__ ull ffma2(ull a, ull b, ull c) {
    ull d;
    asm("fma.rn.f32x2 %0, %1, %2, %3;" : "=l"(d) : "l"(a), "l"(b), "l"(c));
    return d;
}
__device__ __forceinline__ ull add2(ull a, ull b) {
    ull d;
    asm("add.rn.f32x2 %0, %1, %2;" : "=l"(d) : "l"(a), "l"(b));
    return d;
}
__device__ __forceinline__ ull pk(float lo, float hi) {
    ull r;
    asm("mov.b64 %0, {%1, %2};" : "=l"(r) : "f"(lo), "f"(hi));
    return r;
}
__device__ __forceinline__ float hsum2(ull a) {   // lo + hi
    float lo, hi;
    asm("mov.b64 {%0, %1}, %2;" : "=f"(lo), "=f"(hi) : "l"(a));
    return lo + hi;
}
__device__ __forceinline__ float tanhx(float x) {
    float r;
    asm("tanh.approx.f32 %0, %1;" : "=f"(r) : "f"(x));
    return r;
}
__device__ __forceinline__ unsigned smem_u32(const void* p) {
    unsigned a;
    asm("{ .reg .u64 t; cvta.to.shared.u64 t, %1; cvt.u32.u64 %0, t; }"
        : "=r"(a) : "l"(p));
    return a;
}

// Dummy kernel: shifts the ncu capture window (-s 5 -c 1) so rnn_scan lands
// in the profiled slot instead of build_xtab. ~2us cost, diagnostic value.
__global__ void shim_kernel(int* p) { if (p) *p = 0; }

// ---------------------------------------------------------------------------
// Kernel 1: xtab[v][o] = Wx_b[o] + sum_h embed[v][h] * Wx_w[o][h]
// ---------------------------------------------------------------------------
__global__ void build_xtab(const float* __restrict__ embed,
                           const float* __restrict__ Wxw,
                           const float* __restrict__ Wxb) {
    int tid = blockIdx.x * blockDim.x + threadIdx.x;
    if (tid >= NVOC * HID) return;
    int v = tid >> 4;
    int o = tid & 15;
    const float4* er = (const float4*)(embed + v * HID);
    const float4* wr = (const float4*)(Wxw + o * HID);
    float s = Wxb[o];
#pragma unroll
    for (int i = 0; i < 4; i++) {
        float4 e = __ldg(&er[i]);
        float4 w = __ldg(&wr[i]);
        s += e.x * w.x + e.y * w.y + e.z * w.z + e.w * w.w;
    }
    g_xtab[tid] = s;
}

// ---------------------------------------------------------------------------
// Kernel 2: recurrence. NOW 128-thread CTAs: 4 warps per block, one per SMSP
// (1-warp CTAs left 3/4 of the schedulers idle — every CTA's wid=0 warp
// contended for the same SMSP). Per warp: 8 batches; lane = (p = lane>>3,
// bl = lane&7); lane owns h[4p..4p+3] of batch bl. h exchanged via per-warp
// ping-pong SMEM (stride-20 rows -> conflict-free STS.128/LDS.128).
// Token ring (LDG, dist 16) feeds xtab ring (LDG, dist 8).
// ---------------------------------------------------------------------------
__global__ void __launch_bounds__(128) rnn_scan(const int* __restrict__ seq,
                                                const float* __restrict__ Wh) {
    __shared__ float hbuf[4][2][8 * 20];          // [warp][pingpong][8 batches]
    const int lane = threadIdx.x & 31;
    const int wid  = threadIdx.x >> 5;            // 0..3 (one per SMSP)
    const int warp = blockIdx.x * 4 + wid;        // 0..511 global warp
    const int bl = lane & 7;
    const int p  = lane >> 3;

    // zero this warp's read-buffer 0 (h0 = 0)
    for (int i = lane; i < 8 * 20; i += 32) hbuf[wid][0][i] = 0.f;

    const unsigned sb0 = smem_u32(&hbuf[wid][0][0]) + bl * 80;   // bytes
    const unsigned sb1 = smem_u32(&hbuf[wid][1][0]) + bl * 80;

    // Wh rows for my 4 outputs, packed f32x2 along h (32 ull, loop-invariant)
    ull wh[4][8];
#pragma unroll
    for (int i = 0; i < 4; i++) {
        const float4* r = (const float4*)(Wh + (4 * p + i) * HID);
#pragma unroll
        for (int j = 0; j < 4; j++) {
            float4 t = __ldg(&r[j]);
            wh[i][2 * j]     = pk(t.x, t.y);
            wh[i][2 * j + 1] = pk(t.z, t.w);
        }
    }

    const int* myseq = seq + (warp * 8 + bl) * TT;
    const float4* xt = (const float4*)g_xtab;

    // Prime rings: tokring[i] = token[i+8], xpring[i] = xproj[i]
    int   tokring[8];
    float4 xpring[8];
#pragma unroll
    for (int i = 0; i < 8; i++) {
        tokring[i] = __ldg(&myseq[i + 8]);
        xpring[i]  = __ldg(&xt[__ldg(&myseq[i]) * 4 + p]);
    }
    __syncwarp();

#pragma unroll 8
    for (int t = 0; t < TT; t++) {
        const int slot = t & 7;
        float4 cur = xpring[slot];                 // xproj for step t
        int tok = tokring[slot];                   // token for t+8 (arrived)
        xpring[slot] = __ldg(&xt[tok * 4 + p]);    // xproj for t+8
        int tn = t + 16; if (tn > TT - 1) tn = TT - 1;
        tokring[slot] = __ldg(&myseq[tn]);         // token for t+16

        const unsigned rbase = (t & 1) ? sb1 : sb0;
        const unsigned wbase = (t & 1) ? sb0 : sb1;

        // read full h[16] of my batch: 4x 128-bit LDS, direct 64-bit pairs
        ull hp[8];
        asm volatile("ld.shared.v2.b64 {%0,%1},[%2];"
                     : "=l"(hp[0]), "=l"(hp[1]) : "r"(rbase) : "memory");
        asm volatile("ld.shared.v2.b64 {%0,%1},[%2];"
                     : "=l"(hp[2]), "=l"(hp[3]) : "r"(rbase + 16) : "memory");
        asm volatile("ld.shared.v2.b64 {%0,%1},[%2];"
                     : "=l"(hp[4]), "=l"(hp[5]) : "r"(rbase + 32) : "memory");
        asm volatile("ld.shared.v2.b64 {%0,%1},[%2];"
                     : "=l"(hp[6]), "=l"(hp[7]) : "r"(rbase + 48) : "memory");

        // 4 outputs, each as two 4-deep FFMA2 trees
        ull aL0 = ffma2(wh[0][0], hp[0], pk(cur.x, 0.f));
        ull aL1 = ffma2(wh[1][0], hp[0], pk(cur.y, 0.f));
        ull aL2 = ffma2(wh[2][0], hp[0], pk(cur.z, 0.f));
        ull aL3 = ffma2(wh[3][0], hp[0], pk(cur.w, 0.f));
        ull aH0 = ffma2(wh[0][4], hp[4], 0ull);
        ull aH1 = ffma2(wh[1][4], hp[4], 0ull);
        ull aH2 = ffma2(wh[2][4], hp[4], 0ull);
        ull aH3 = ffma2(wh[3][4], hp[4], 0ull);
#pragma unroll
        for (int q = 1; q < 4; q++) {
            aL0 = ffma2(wh[0][q], hp[q], aL0);
            aL1 = ffma2(wh[1][q], hp[q], aL1);
            aL2 = ffma2(wh[2][q], hp[q], aL2);
            aL3 = ffma2(wh[3][q], hp[q], aL3);
            aH0 = ffma2(wh[0][q + 4], hp[q + 4], aH0);
            aH1 = ffma2(wh[1][q + 4], hp[q + 4], aH1);
            aH2 = ffma2(wh[2][q + 4], hp[q + 4], aH2);
            aH3 = ffma2(wh[3][q + 4], hp[q + 4], aH3);
        }
        float h0 = tanhx(hsum2(add2(aL0, aH0)));
        float h1 = tanhx(hsum2(add2(aL1, aH1)));
        float h2 = tanhx(hsum2(add2(aL2, aH2)));
        float h3 = tanhx(hsum2(add2(aL3, aH3)));

        asm volatile("st.shared.v4.b32 [%0],{%1,%2,%3,%4};"
                     :: "r"(wbase + 16 * p), "f"(h0), "f"(h1), "f"(h2), "f"(h3)
                     : "memory");
        __syncwarp();
    }

    // final h lives in ping-pong buffer 0 (TT even); lane rereads its own 4
    float4 hf = *(const float4*)&hbuf[wid][0][bl * 20 + 4 * p];
    int b = warp * 8 + bl;
    *(float4*)(g_hfin + b * HID + 4 * p) = hf;
}

// ---------------------------------------------------------------------------
// Kernel 3: out[b][v] = out_b[v] + sum_h hfin[b][h] * out_w[v][h]
// 2000 warps; lane owns 4 consecutive v (weights in regs, loaded once).
// Broadcast h loads depth-2 prefetch; streaming STG.128.
// ---------------------------------------------------------------------------
__global__ void __launch_bounds__(128) out_proj(const float* __restrict__ outw,
                                                const float* __restrict__ outb,
                                                float* __restrict__ out) {
    int gw   = (blockIdx.x * blockDim.x + threadIdx.x) >> 5;   // 0..1999
    int lane = threadIdx.x & 31;
    int vgrp = gw % 250;
    int bgrp = gw / 250;                                       // 0..7
    int v0 = vgrp * 128 + lane * 4;

    ull w[4][8];
#pragma unroll
    for (int i = 0; i < 4; i++) {
        const float4* r = (const float4*)(outw + (v0 + i) * HID);
#pragma unroll
        for (int j = 0; j < 4; j++) {
            float4 t = __ldg(&r[j]);
            w[i][2 * j]     = pk(t.x, t.y);
            w[i][2 * j + 1] = pk(t.z, t.w);
        }
    }
    float4 ob = __ldg((const float4*)(outb + v0));

    const int bcnt = BATCH / 8;                                // 512
    const int b0 = bgrp * bcnt;
    const float4* hf = (const float4*)g_hfin;

    float4 ha0 = __ldg(&hf[(size_t)b0 * 4 + 0]);
    float4 ha1 = __ldg(&hf[(size_t)b0 * 4 + 1]);
    float4 ha2 = __ldg(&hf[(size_t)b0 * 4 + 2]);
    float4 ha3 = __ldg(&hf[(size_t)b0 * 4 + 3]);
    float4 hb0 = __ldg(&hf[(size_t)(b0 + 1) * 4 + 0]);
    float4 hb1 = __ldg(&hf[(size_t)(b0 + 1) * 4 + 1]);
    float4 hb2 = __ldg(&hf[(size_t)(b0 + 1) * 4 + 2]);
    float4 hb3 = __ldg(&hf[(size_t)(b0 + 1) * 4 + 3]);

#pragma unroll 2
    for (int b = b0; b < b0 + bcnt; b++) {
        int bn = (b + 2 < b0 + bcnt) ? (b + 2) : b;
        float4 hn0 = __ldg(&hf[(size_t)bn * 4 + 0]);
        float4 hn1 = __ldg(&hf[(size_t)bn * 4 + 1]);
        float4 hn2 = __ldg(&hf[(size_t)bn * 4 + 2]);
        float4 hn3 = __ldg(&hf[(size_t)bn * 4 + 3]);

        ull hp[8];
        hp[0] = pk(ha0.x, ha0.y); hp[1] = pk(ha0.z, ha0.w);
        hp[2] = pk(ha1.x, ha1.y); hp[3] = pk(ha1.z, ha1.w);
        hp[4] = pk(ha2.x, ha2.y); hp[5] = pk(ha2.z, ha2.w);
        hp[6] = pk(ha3.x, ha3.y); hp[7] = pk(ha3.z, ha3.w);

        ull aL0 = ffma2(w[0][0], hp[0], pk(ob.x, 0.f));
        ull aL1 = ffma2(w[1][0], hp[0], pk(ob.y, 0.f));
        ull aL2 = ffma2(w[2][0], hp[0], pk(ob.z, 0.f));
        ull aL3 = ffma2(w[3][0], hp[0], pk(ob.w, 0.f));
        ull aH0 = ffma2(w[0][4], hp[4], 0ull);
        ull aH1 = ffma2(w[1][4], hp[4], 0ull);
        ull aH2 = ffma2(w[2][4], hp[4], 0ull);
        ull aH3 = ffma2(w[3][4], hp[4], 0ull);
#pragma unroll
        for (int q = 1; q < 4; q++) {
            aL0 = ffma2(w[0][q], hp[q], aL0);
            aL1 = ffma2(w[1][q], hp[q], aL1);
            aL2 = ffma2(w[2][q], hp[q], aL2);
            aL3 = ffma2(w[3][q], hp[q], aL3);
            aH0 = ffma2(w[0][q + 4], hp[q + 4], aH0);
            aH1 = ffma2(w[1][q + 4], hp[q + 4], aH1);
            aH2 = ffma2(w[2][q + 4], hp[q + 4], aH2);
            aH3 = ffma2(w[3][q + 4], hp[q + 4], aH3);
        }
        float4 res = make_float4(hsum2(add2(aL0, aH0)), hsum2(add2(aL1, aH1)),
                                 hsum2(add2(aL2, aH2)), hsum2(add2(aL3, aH3)));
        __stcs((float4*)(out + (size_t)b * NVOC + v0), res);

        ha0 = hb0; ha1 = hb1; ha2 = hb2; ha3 = hb3;
        hb0 = hn0; hb1 = hn1; hb2 = hn2; hb3 = hn3;
    }
}

// ---------------------------------------------------------------------------
extern "C" void kernel_launch(void* const* d_in, const int* in_sizes, int n_in,
                              void* d_out, int out_size) {
    const int*   seq   = (const int*)d_in[0];
    const float* embed = (const float*)d_in[1];
    const float* Wh    = (const float*)d_in[2];
    const float* Wxw   = (const float*)d_in[3];
    const float* Wxb   = (const float*)d_in[4];
    const float* outw  = (const float*)d_in[5];
    const float* outb  = (const float*)d_in[6];
    float* out = (float*)d_out;

    shim_kernel<<<1, 32>>>(nullptr);   // shifts ncu window onto rnn_scan
    build_xtab<<<(NVOC * HID + 255) / 256, 256>>>(embed, Wxw, Wxb);
    rnn_scan<<<BATCH / 32, 128>>>(seq, Wh);
    out_proj<<<500, 128>>>(outw, outb, out);
}

// round 6
// speedup vs baseline: 1.2059x; 1.2059x over previous
#include <cuda_runtime.h>
#include <cuda_bf16.h>

#define BATCH 4096
#define TT    1024
#define NVOC  32000
#define HID   16

typedef unsigned long long ull;

// Scratch (device globals: allocation-free rule)
__device__ float g_xtab[NVOC * HID];   // 2MB: precomputed x-projection per token
__device__ float g_hfin[BATCH * HID];  // 256KB: final hidden states

// ---- packed f32x2 helpers on 64-bit registers ----
__device__ __forceinline__ ull ffma2(ull a, ull b, ull c) {
    ull d;
    asm("fma.rn.f32x2 %0, %1, %2, %3;" : "=l"(d) : "l"(a), "l"(b), "l"(c));
    return d;
}
__device__ __forceinline__ ull add2(ull a, ull b) {
    ull d;
    asm("add.rn.f32x2 %0, %1, %2;" : "=l"(d) : "l"(a), "l"(b));
    return d;
}
__device__ __forceinline__ ull pk(float lo, float hi) {
    ull r;
    asm("mov.b64 %0, {%1, %2};" : "=l"(r) : "f"(lo), "f"(hi));
    return r;
}
__device__ __forceinline__ float hsum2(ull a) {   // lo + hi
    float lo, hi;
    asm("mov.b64 {%0, %1}, %2;" : "=f"(lo), "=f"(hi) : "l"(a));
    return lo + hi;
}
__device__ __forceinline__ float tanhx(float x) {
    float r;
    asm("tanh.approx.f32 %0, %1;" : "=f"(r) : "f"(x));
    return r;
}
__device__ __forceinline__ unsigned smem_u32(const void* p) {
    unsigned a;
    asm("{ .reg .u64 t; cvta.to.shared.u64 t, %1; cvt.u32.u64 %0, t; }"
        : "=r"(a) : "l"(p));
    return a;
}

// ---------------------------------------------------------------------------
// Kernel 1: xtab[v][o] = Wx_b[o] + sum_h embed[v][h] * Wx_w[o][h]
// ---------------------------------------------------------------------------
__global__ void build_xtab(const float* __restrict__ embed,
                           const float* __restrict__ Wxw,
                           const float* __restrict__ Wxb) {
    int tid = blockIdx.x * blockDim.x + threadIdx.x;
    if (tid >= NVOC * HID) return;
    int v = tid >> 4;
    int o = tid & 15;
    const float4* er = (const float4*)(embed + v * HID);
    const float4* wr = (const float4*)(Wxw + o * HID);
    float s = Wxb[o];
#pragma unroll
    for (int i = 0; i < 4; i++) {
        float4 e = __ldg(&er[i]);
        float4 w = __ldg(&wr[i]);
        s += e.x * w.x + e.y * w.y + e.z * w.z + e.w * w.w;
    }
    g_xtab[tid] = s;
}

// ---------------------------------------------------------------------------
// Kernel 2: recurrence. 128-thread CTAs (one warp per SMSP). Per warp:
// 8 batches; lane = (p = lane>>3, bl = lane&7); lane owns h[4p..4p+3] of
// batch bl. h exchanged via per-warp ping-pong SMEM (stride-20 rows ->
// conflict-free STS.128/LDS.128). Token ring (dist 16) feeds xtab ring (8).
// ---------------------------------------------------------------------------
__global__ void __launch_bounds__(128) rnn_scan(const int* __restrict__ seq,
                                                const float* __restrict__ Wh) {
    __shared__ float hbuf[4][2][8 * 20];          // [warp][pingpong][8 batches]
    const int lane = threadIdx.x & 31;
    const int wid  = threadIdx.x >> 5;            // 0..3
    const int warp = blockIdx.x * 4 + wid;        // 0..511 global warp
    const int bl = lane & 7;
    const int p  = lane >> 3;

    for (int i = lane; i < 8 * 20; i += 32) hbuf[wid][0][i] = 0.f;

    const unsigned sb0 = smem_u32(&hbuf[wid][0][0]) + bl * 80;   // bytes
    const unsigned sb1 = smem_u32(&hbuf[wid][1][0]) + bl * 80;

    ull wh[4][8];
#pragma unroll
    for (int i = 0; i < 4; i++) {
        const float4* r = (const float4*)(Wh + (4 * p + i) * HID);
#pragma unroll
        for (int j = 0; j < 4; j++) {
            float4 t = __ldg(&r[j]);
            wh[i][2 * j]     = pk(t.x, t.y);
            wh[i][2 * j + 1] = pk(t.z, t.w);
        }
    }

    const int* myseq = seq + (warp * 8 + bl) * TT;
    const float4* xt = (const float4*)g_xtab;

    int   tokring[8];
    float4 xpring[8];
#pragma unroll
    for (int i = 0; i < 8; i++) {
        tokring[i] = __ldg(&myseq[i + 8]);
        xpring[i]  = __ldg(&xt[__ldg(&myseq[i]) * 4 + p]);
    }
    __syncwarp();

#pragma unroll 8
    for (int t = 0; t < TT; t++) {
        const int slot = t & 7;
        float4 cur = xpring[slot];
        int tok = tokring[slot];
        xpring[slot] = __ldg(&xt[tok * 4 + p]);
        int tn = t + 16; if (tn > TT - 1) tn = TT - 1;
        tokring[slot] = __ldg(&myseq[tn]);

        const unsigned rbase = (t & 1) ? sb1 : sb0;
        const unsigned wbase = (t & 1) ? sb0 : sb1;

        ull hp[8];
        asm volatile("ld.shared.v2.b64 {%0,%1},[%2];"
                     : "=l"(hp[0]), "=l"(hp[1]) : "r"(rbase) : "memory");
        asm volatile("ld.shared.v2.b64 {%0,%1},[%2];"
                     : "=l"(hp[2]), "=l"(hp[3]) : "r"(rbase + 16) : "memory");
        asm volatile("ld.shared.v2.b64 {%0,%1},[%2];"
                     : "=l"(hp[4]), "=l"(hp[5]) : "r"(rbase + 32) : "memory");
        asm volatile("ld.shared.v2.b64 {%0,%1},[%2];"
                     : "=l"(hp[6]), "=l"(hp[7]) : "r"(rbase + 48) : "memory");

        ull aL0 = ffma2(wh[0][0], hp[0], pk(cur.x, 0.f));
        ull aL1 = ffma2(wh[1][0], hp[0], pk(cur.y, 0.f));
        ull aL2 = ffma2(wh[2][0], hp[0], pk(cur.z, 0.f));
        ull aL3 = ffma2(wh[3][0], hp[0], pk(cur.w, 0.f));
        ull aH0 = ffma2(wh[0][4], hp[4], 0ull);
        ull aH1 = ffma2(wh[1][4], hp[4], 0ull);
        ull aH2 = ffma2(wh[2][4], hp[4], 0ull);
        ull aH3 = ffma2(wh[3][4], hp[4], 0ull);
#pragma unroll
        for (int q = 1; q < 4; q++) {
            aL0 = ffma2(wh[0][q], hp[q], aL0);
            aL1 = ffma2(wh[1][q], hp[q], aL1);
            aL2 = ffma2(wh[2][q], hp[q], aL2);
            aL3 = ffma2(wh[3][q], hp[q], aL3);
            aH0 = ffma2(wh[0][q + 4], hp[q + 4], aH0);
            aH1 = ffma2(wh[1][q + 4], hp[q + 4], aH1);
            aH2 = ffma2(wh[2][q + 4], hp[q + 4], aH2);
            aH3 = ffma2(wh[3][q + 4], hp[q + 4], aH3);
        }
        float h0 = tanhx(hsum2(add2(aL0, aH0)));
        float h1 = tanhx(hsum2(add2(aL1, aH1)));
        float h2 = tanhx(hsum2(add2(aL2, aH2)));
        float h3 = tanhx(hsum2(add2(aL3, aH3)));

        asm volatile("st.shared.v4.b32 [%0],{%1,%2,%3,%4};"
                     :: "r"(wbase + 16 * p), "f"(h0), "f"(h1), "f"(h2), "f"(h3)
                     : "memory");
        __syncwarp();
    }

    float4 hf = *(const float4*)&hbuf[wid][0][bl * 20 + 4 * p];
    int b = warp * 8 + bl;
    *(float4*)(g_hfin + b * HID + 4 * p) = hf;
}

// ---------------------------------------------------------------------------
// Kernel 3: out[b][v] = out_b[v] + sum_h hfin[b][h] * out_w[v][h]
// R6: 8000 warps (was 2000) -> ~54 warps/SM. Warp = (vgrp of 128 v,
// bgrp of 128 b). Lane owns 4 consecutive v; weights live in regs (loaded
// once per warp; out_w is L2-resident so the 32x re-read is noise vs the
// 512MB output write). Latency hidden by occupancy; depth-2 h prefetch kept.
// ---------------------------------------------------------------------------
#define BGRPS 32
__global__ void __launch_bounds__(128) out_proj(const float* __restrict__ outw,
                                                const float* __restrict__ outb,
                                                float* __restrict__ out) {
    int gw   = (blockIdx.x * blockDim.x + threadIdx.x) >> 5;   // 0..7999
    int lane = threadIdx.x & 31;
    int vgrp = gw % 250;
    int bgrp = gw / 250;                                       // 0..31
    int v0 = vgrp * 128 + lane * 4;

    ull w[4][8];
#pragma unroll
    for (int i = 0; i < 4; i++) {
        const float4* r = (const float4*)(outw + (v0 + i) * HID);
#pragma unroll
        for (int j = 0; j < 4; j++) {
            float4 t = __ldg(&r[j]);
            w[i][2 * j]     = pk(t.x, t.y);
            w[i][2 * j + 1] = pk(t.z, t.w);
        }
    }
    float4 ob = __ldg((const float4*)(outb + v0));

    const int bcnt = BATCH / BGRPS;                            // 128
    const int b0 = bgrp * bcnt;
    const float4* hf = (const float4*)g_hfin;

    float4 ha0 = __ldg(&hf[(size_t)b0 * 4 + 0]);
    float4 ha1 = __ldg(&hf[(size_t)b0 * 4 + 1]);
    float4 ha2 = __ldg(&hf[(size_t)b0 * 4 + 2]);
    float4 ha3 = __ldg(&hf[(size_t)b0 * 4 + 3]);
    float4 hb0 = __ldg(&hf[(size_t)(b0 + 1) * 4 + 0]);
    float4 hb1 = __ldg(&hf[(size_t)(b0 + 1) * 4 + 1]);
    float4 hb2 = __ldg(&hf[(size_t)(b0 + 1) * 4 + 2]);
    float4 hb3 = __ldg(&hf[(size_t)(b0 + 1) * 4 + 3]);

#pragma unroll 2
    for (int b = b0; b < b0 + bcnt; b++) {
        int bn = (b + 2 < b0 + bcnt) ? (b + 2) : b;
        float4 hn0 = __ldg(&hf[(size_t)bn * 4 + 0]);
        float4 hn1 = __ldg(&hf[(size_t)bn * 4 + 1]);
        float4 hn2 = __ldg(&hf[(size_t)bn * 4 + 2]);
        float4 hn3 = __ldg(&hf[(size_t)bn * 4 + 3]);

        ull hp[8];
        hp[0] = pk(ha0.x, ha0.y); hp[1] = pk(ha0.z, ha0.w);
        hp[2] = pk(ha1.x, ha1.y); hp[3] = pk(ha1.z, ha1.w);
        hp[4] = pk(ha2.x, ha2.y); hp[5] = pk(ha2.z, ha2.w);
        hp[6] = pk(ha3.x, ha3.y); hp[7] = pk(ha3.z, ha3.w);

        ull aL0 = ffma2(w[0][0], hp[0], pk(ob.x, 0.f));
        ull aL1 = ffma2(w[1][0], hp[0], pk(ob.y, 0.f));
        ull aL2 = ffma2(w[2][0], hp[0], pk(ob.z, 0.f));
        ull aL3 = ffma2(w[3][0], hp[0], pk(ob.w, 0.f));
        ull aH0 = ffma2(w[0][4], hp[4], 0ull);
        ull aH1 = ffma2(w[1][4], hp[4], 0ull);
        ull aH2 = ffma2(w[2][4], hp[4], 0ull);
        ull aH3 = ffma2(w[3][4], hp[4], 0ull);
#pragma unroll
        for (int q = 1; q < 4; q++) {
            aL0 = ffma2(w[0][q], hp[q], aL0);
            aL1 = ffma2(w[1][q], hp[q], aL1);
            aL2 = ffma2(w[2][q], hp[q], aL2);
            aL3 = ffma2(w[3][q], hp[q], aL3);
            aH0 = ffma2(w[0][q + 4], hp[q + 4], aH0);
            aH1 = ffma2(w[1][q + 4], hp[q + 4], aH1);
            aH2 = ffma2(w[2][q + 4], hp[q + 4], aH2);
            aH3 = ffma2(w[3][q + 4], hp[q + 4], aH3);
        }
        float4 res = make_float4(hsum2(add2(aL0, aH0)), hsum2(add2(aL1, aH1)),
                                 hsum2(add2(aL2, aH2)), hsum2(add2(aL3, aH3)));
        __stcs((float4*)(out + (size_t)b * NVOC + v0), res);

        ha0 = hb0; ha1 = hb1; ha2 = hb2; ha3 = hb3;
        hb0 = hn0; hb1 = hn1; hb2 = hn2; hb3 = hn3;
    }
}

// ---------------------------------------------------------------------------
extern "C" void kernel_launch(void* const* d_in, const int* in_sizes, int n_in,
                              void* d_out, int out_size) {
    const int*   seq   = (const int*)d_in[0];
    const float* embed = (const float*)d_in[1];
    const float* Wh    = (const float*)d_in[2];
    const float* Wxw   = (const float*)d_in[3];
    const float* Wxb   = (const float*)d_in[4];
    const float* outw  = (const float*)d_in[5];
    const float* outb  = (const float*)d_in[6];
    float* out = (float*)d_out;

    build_xtab<<<(NVOC * HID + 255) / 256, 256>>>(embed, Wxw, Wxb);
    rnn_scan<<<BATCH / 32, 128>>>(seq, Wh);
    out_proj<<<250 * BGRPS * 32 / 128, 128>>>(outw, outb, out);   // 2000 blocks
}

// round 7
// speedup vs baseline: 1.3654x; 1.1322x over previous
#include <cuda_runtime.h>
#include <cuda_bf16.h>

#define BATCH 4096
#define TT    1024
#define NVOC  32000
#define HID   16

typedef unsigned long long ull;

// Scratch (device globals: allocation-free rule)
__device__ float g_xtab[NVOC * HID];   // 2MB: precomputed x-projection per token
__device__ float g_hfin[BATCH * HID];  // 256KB: final hidden states

// ---- packed f32x2 helpers on 64-bit registers ----
__device__ __forceinline__ ull ffma2(ull a, ull b, ull c) {
    ull d;
    asm("fma.rn.f32x2 %0, %1, %2, %3;" : "=l"(d) : "l"(a), "l"(b), "l"(c));
    return d;
}
__device__ __forceinline__ ull add2(ull a, ull b) {
    ull d;
    asm("add.rn.f32x2 %0, %1, %2;" : "=l"(d) : "l"(a), "l"(b));
    return d;
}
__device__ __forceinline__ ull pk(float lo, float hi) {
    ull r;
    asm("mov.b64 %0, {%1, %2};" : "=l"(r) : "f"(lo), "f"(hi));
    return r;
}
__device__ __forceinline__ float hsum2(ull a) {   // lo + hi
    float lo, hi;
    asm("mov.b64 {%0, %1}, %2;" : "=f"(lo), "=f"(hi) : "l"(a));
    return lo + hi;
}
__device__ __forceinline__ float tanhx(float x) {
    float r;
    asm("tanh.approx.f32 %0, %1;" : "=f"(r) : "f"(x));
    return r;
}
__device__ __forceinline__ unsigned smem_u32(const void* p) {
    unsigned a;
    asm("{ .reg .u64 t; cvta.to.shared.u64 t, %1; cvt.u32.u64 %0, t; }"
        : "=r"(a) : "l"(p));
    return a;
}

// ---------------------------------------------------------------------------
// Kernel 1: xtab[v][o] = Wx_b[o] + sum_h embed[v][h] * Wx_w[o][h]
// ---------------------------------------------------------------------------
__global__ void build_xtab(const float* __restrict__ embed,
                           const float* __restrict__ Wxw,
                           const float* __restrict__ Wxb) {
    int tid = blockIdx.x * blockDim.x + threadIdx.x;
    if (tid >= NVOC * HID) return;
    int v = tid >> 4;
    int o = tid & 15;
    const float4* er = (const float4*)(embed + v * HID);
    const float4* wr = (const float4*)(Wxw + o * HID);
    float s = Wxb[o];
#pragma unroll
    for (int i = 0; i < 4; i++) {
        float4 e = __ldg(&er[i]);
        float4 w = __ldg(&wr[i]);
        s += e.x * w.x + e.y * w.y + e.z * w.z + e.w * w.w;
    }
    g_xtab[tid] = s;
}

// ---------------------------------------------------------------------------
// Kernel 2: recurrence (unchanged from R5/R6 — ~80us). 128-thread CTAs, one
// warp per SMSP; warp handles 8 batches; h exchanged via per-warp ping-pong
// SMEM (stride-20 conflict-free); token ring (16) feeds xtab ring (8).
// ---------------------------------------------------------------------------
__global__ void __launch_bounds__(128) rnn_scan(const int* __restrict__ seq,
                                                const float* __restrict__ Wh) {
    __shared__ float hbuf[4][2][8 * 20];
    const int lane = threadIdx.x & 31;
    const int wid  = threadIdx.x >> 5;
    const int warp = blockIdx.x * 4 + wid;
    const int bl = lane & 7;
    const int p  = lane >> 3;

    for (int i = lane; i < 8 * 20; i += 32) hbuf[wid][0][i] = 0.f;

    const unsigned sb0 = smem_u32(&hbuf[wid][0][0]) + bl * 80;
    const unsigned sb1 = smem_u32(&hbuf[wid][1][0]) + bl * 80;

    ull wh[4][8];
#pragma unroll
    for (int i = 0; i < 4; i++) {
        const float4* r = (const float4*)(Wh + (4 * p + i) * HID);
#pragma unroll
        for (int j = 0; j < 4; j++) {
            float4 t = __ldg(&r[j]);
            wh[i][2 * j]     = pk(t.x, t.y);
            wh[i][2 * j + 1] = pk(t.z, t.w);
        }
    }

    const int* myseq = seq + (warp * 8 + bl) * TT;
    const float4* xt = (const float4*)g_xtab;

    int   tokring[8];
    float4 xpring[8];
#pragma unroll
    for (int i = 0; i < 8; i++) {
        tokring[i] = __ldg(&myseq[i + 8]);
        xpring[i]  = __ldg(&xt[__ldg(&myseq[i]) * 4 + p]);
    }
    __syncwarp();

#pragma unroll 8
    for (int t = 0; t < TT; t++) {
        const int slot = t & 7;
        float4 cur = xpring[slot];
        int tok = tokring[slot];
        xpring[slot] = __ldg(&xt[tok * 4 + p]);
        int tn = t + 16; if (tn > TT - 1) tn = TT - 1;
        tokring[slot] = __ldg(&myseq[tn]);

        const unsigned rbase = (t & 1) ? sb1 : sb0;
        const unsigned wbase = (t & 1) ? sb0 : sb1;

        ull hp[8];
        asm volatile("ld.shared.v2.b64 {%0,%1},[%2];"
                     : "=l"(hp[0]), "=l"(hp[1]) : "r"(rbase) : "memory");
        asm volatile("ld.shared.v2.b64 {%0,%1},[%2];"
                     : "=l"(hp[2]), "=l"(hp[3]) : "r"(rbase + 16) : "memory");
        asm volatile("ld.shared.v2.b64 {%0,%1},[%2];"
                     : "=l"(hp[4]), "=l"(hp[5]) : "r"(rbase + 32) : "memory");
        asm volatile("ld.shared.v2.b64 {%0,%1},[%2];"
                     : "=l"(hp[6]), "=l"(hp[7]) : "r"(rbase + 48) : "memory");

        ull aL0 = ffma2(wh[0][0], hp[0], pk(cur.x, 0.f));
        ull aL1 = ffma2(wh[1][0], hp[0], pk(cur.y, 0.f));
        ull aL2 = ffma2(wh[2][0], hp[0], pk(cur.z, 0.f));
        ull aL3 = ffma2(wh[3][0], hp[0], pk(cur.w, 0.f));
        ull aH0 = ffma2(wh[0][4], hp[4], 0ull);
        ull aH1 = ffma2(wh[1][4], hp[4], 0ull);
        ull aH2 = ffma2(wh[2][4], hp[4], 0ull);
        ull aH3 = ffma2(wh[3][4], hp[4], 0ull);
#pragma unroll
        for (int q = 1; q < 4; q++) {
            aL0 = ffma2(wh[0][q], hp[q], aL0);
            aL1 = ffma2(wh[1][q], hp[q], aL1);
            aL2 = ffma2(wh[2][q], hp[q], aL2);
            aL3 = ffma2(wh[3][q], hp[q], aL3);
            aH0 = ffma2(wh[0][q + 4], hp[q + 4], aH0);
            aH1 = ffma2(wh[1][q + 4], hp[q + 4], aH1);
            aH2 = ffma2(wh[2][q + 4], hp[q + 4], aH2);
            aH3 = ffma2(wh[3][q + 4], hp[q + 4], aH3);
        }
        float h0 = tanhx(hsum2(add2(aL0, aH0)));
        float h1 = tanhx(hsum2(add2(aL1, aH1)));
        float h2 = tanhx(hsum2(add2(aL2, aH2)));
        float h3 = tanhx(hsum2(add2(aL3, aH3)));

        asm volatile("st.shared.v4.b32 [%0],{%1,%2,%3,%4};"
                     :: "r"(wbase + 16 * p), "f"(h0), "f"(h1), "f"(h2), "f"(h3)
                     : "memory");
        __syncwarp();
    }

    float4 hf = *(const float4*)&hbuf[wid][0][bl * 20 + 4 * p];
    int b = warp * 8 + bl;
    *(float4*)(g_hfin + b * HID + 4 * p) = hf;
}

// ---------------------------------------------------------------------------
// Kernel 3: out[b][v] = out_b[v] + sum_h hfin[b][h] * out_w[v][h]
// R7 redesign: block = (128-v weight tile) x (512 batches). The 512x16 f32
// h-slice (32KB) is staged into SMEM once per block; inner loop reads h via
// broadcast LDS (29cyc, hidden by ILP) instead of 260cyc L2-hit LDG. No
// prefetch registers -> lower reg pressure -> more resident warps. 4 warps
// split the 512 batches. Grid 250 x 8 = 2000 blocks.
// ---------------------------------------------------------------------------
#define OB_BATCH 512
__global__ void __launch_bounds__(128) out_proj(const float* __restrict__ outw,
                                                const float* __restrict__ outb,
                                                float* __restrict__ out) {
    __shared__ float4 s_h[OB_BATCH * 4];        // [batch][4xfloat4] = 32KB
    const int tid  = threadIdx.x;
    const int lane = tid & 31;
    const int wid  = tid >> 5;                  // 0..3
    const int vgrp = blockIdx.x % 250;
    const int bgrp = blockIdx.x / 250;          // 0..7
    const int v0 = vgrp * 128 + lane * 4;
    const int b0 = bgrp * OB_BATCH;

    // cooperative h staging: 2048 float4 loads, fully coalesced
    {
        const float4* src = (const float4*)(g_hfin + (size_t)b0 * HID);
#pragma unroll 4
        for (int i = tid; i < OB_BATCH * 4; i += 128) s_h[i] = __ldg(&src[i]);
    }

    // weight tile: lane owns 4 consecutive v rows (64 regs, loop-invariant)
    ull w[4][8];
#pragma unroll
    for (int i = 0; i < 4; i++) {
        const float4* r = (const float4*)(outw + (v0 + i) * HID);
#pragma unroll
        for (int j = 0; j < 4; j++) {
            float4 t = __ldg(&r[j]);
            w[i][2 * j]     = pk(t.x, t.y);
            w[i][2 * j + 1] = pk(t.z, t.w);
        }
    }
    float4 ob = __ldg((const float4*)(outb + v0));
    __syncthreads();

    const unsigned hsbase = smem_u32(s_h);
    const int bcnt = OB_BATCH / 4;              // 128 per warp
    const int wb0 = b0 + wid * bcnt;
    unsigned haddr = hsbase + (unsigned)(wid * bcnt) * 64;   // 64B per batch
    float* dst = out + (size_t)wb0 * NVOC + v0;

#pragma unroll 4
    for (int i = 0; i < bcnt; i++) {
        // broadcast LDS of this batch's h[16] as 64-bit pairs
        ull hp[8];
        asm volatile("ld.shared.v2.b64 {%0,%1},[%2];"
                     : "=l"(hp[0]), "=l"(hp[1]) : "r"(haddr));
        asm volatile("ld.shared.v2.b64 {%0,%1},[%2];"
                     : "=l"(hp[2]), "=l"(hp[3]) : "r"(haddr + 16));
        asm volatile("ld.shared.v2.b64 {%0,%1},[%2];"
                     : "=l"(hp[4]), "=l"(hp[5]) : "r"(haddr + 32));
        asm volatile("ld.shared.v2.b64 {%0,%1},[%2];"
                     : "=l"(hp[6]), "=l"(hp[7]) : "r"(haddr + 48));

        ull aL0 = ffma2(w[0][0], hp[0], pk(ob.x, 0.f));
        ull aL1 = ffma2(w[1][0], hp[0], pk(ob.y, 0.f));
        ull aL2 = ffma2(w[2][0], hp[0], pk(ob.z, 0.f));
        ull aL3 = ffma2(w[3][0], hp[0], pk(ob.w, 0.f));
        ull aH0 = ffma2(w[0][4], hp[4], 0ull);
        ull aH1 = ffma2(w[1][4], hp[4], 0ull);
        ull aH2 = ffma2(w[2][4], hp[4], 0ull);
        ull aH3 = ffma2(w[3][4], hp[4], 0ull);
#pragma unroll
        for (int q = 1; q < 4; q++) {
            aL0 = ffma2(w[0][q], hp[q], aL0);
            aL1 = ffma2(w[1][q], hp[q], aL1);
            aL2 = ffma2(w[2][q], hp[q], aL2);
            aL3 = ffma2(w[3][q], hp[q], aL3);
            aH0 = ffma2(w[0][q + 4], hp[q + 4], aH0);
            aH1 = ffma2(w[1][q + 4], hp[q + 4], aH1);
            aH2 = ffma2(w[2][q + 4], hp[q + 4], aH2);
            aH3 = ffma2(w[3][q + 4], hp[q + 4], aH3);
        }
        float4 res = make_float4(hsum2(add2(aL0, aH0)), hsum2(add2(aL1, aH1)),
                                 hsum2(add2(aL2, aH2)), hsum2(add2(aL3, aH3)));
        __stcs((float4*)dst, res);

        haddr += 64;
        dst += NVOC;
    }
}

// ---------------------------------------------------------------------------
extern "C" void kernel_launch(void* const* d_in, const int* in_sizes, int n_in,
                              void* d_out, int out_size) {
    const int*   seq   = (const int*)d_in[0];
    const float* embed = (const float*)d_in[1];
    const float* Wh    = (const float*)d_in[2];
    const float* Wxw   = (const float*)d_in[3];
    const float* Wxb   = (const float*)d_in[4];
    const float* outw  = (const float*)d_in[5];
    const float* outb  = (const float*)d_in[6];
    float* out = (float*)d_out;

    build_xtab<<<(NVOC * HID + 255) / 256, 256>>>(embed, Wxw, Wxb);
    rnn_scan<<<BATCH / 32, 128>>>(seq, Wh);
    out_proj<<<250 * (BATCH / OB_BATCH), 128>>>(outw, outb, out);  // 2000 blocks
}